// round 3
// baseline (speedup 1.0000x reference)
#include <cuda_runtime.h>
#include <math_constants.h>

#define BB 4
#define CC 64
#define NN 16384
#define KK 16
#define CO 64

// Scratch (device globals — no allocation allowed in kernel_launch)
__device__ float g_yT[BB*NN*CO];    // y transposed: [b*N+n][o]
__device__ float g_zT[BB*NN*CO];    // z transposed: [b*N+n][o]
__device__ float g_hmax[BB*NN*CO];  // max_k h = y - min_k z_e
__device__ float g_hmin[BB*NN*CO];  // min_k h = y - max_k z_e
__device__ float g_sum[CO];
__device__ float g_sumsq[CO];
__device__ float g_scale[CO];
__device__ float g_shift[CO];

__global__ void k_zero() {
    int t = threadIdx.x;
    if (t < CO) { g_sum[t] = 0.f; g_sumsq[t] = 0.f; }
}

// ---------------------------------------------------------------------------
// Kernel A: per-batch GEMMs.  yT[bn][o] = sum_c (W1+W2)[o][c]*x[b][c][n]
//                             zT[bn][o] = sum_c  W2[o][c]    *x[b][c][n]
// Block: 256 threads, tile 64 n x 64 o, register tile 4x4.
// ---------------------------------------------------------------------------
__global__ void __launch_bounds__(256) k_gemm(const float* __restrict__ x,
                                              const float* __restrict__ W) {
    __shared__ float ws[CC*CO];   // [c][o]  (W1+W2) transposed
    __shared__ float w2[CC*CO];   // [c][o]  W2 transposed
    __shared__ float xs[CC*64];   // [c][n_local]
    int tid = threadIdx.x;
    int b = blockIdx.y;
    int n0 = blockIdx.x * 64;

    for (int i = tid; i < CC*CO; i += 256) {
        int o = i >> 6, c = i & 63;
        float w1v = W[o*(2*CC) + c];
        float w2v = W[o*(2*CC) + CC + c];
        ws[c*CO + o] = w1v + w2v;
        w2[c*CO + o] = w2v;
    }
    const float* xb = x + (size_t)b*CC*NN + n0;
    for (int i = tid; i < CC*64; i += 256) {
        int c = i >> 6, nl = i & 63;
        xs[c*64 + nl] = xb[(size_t)c*NN + nl];
    }
    __syncthreads();

    int tx = tid & 15;   // -> o0 = tx*4
    int ty = tid >> 4;   // -> n0l = ty*4
    float ay[4][4], az[4][4];
    #pragma unroll
    for (int j = 0; j < 4; j++)
        #pragma unroll
        for (int i = 0; i < 4; i++) { ay[j][i] = 0.f; az[j][i] = 0.f; }

    const float4* ws4 = (const float4*)ws;
    const float4* w24 = (const float4*)w2;
    const float4* xs4 = (const float4*)xs;
    #pragma unroll 8
    for (int c = 0; c < CC; c++) {
        float4 wv = ws4[c*16 + tx];
        float4 zv = w24[c*16 + tx];
        float4 xv = xs4[c*16 + ty];
        float wq[4] = {wv.x, wv.y, wv.z, wv.w};
        float zq[4] = {zv.x, zv.y, zv.z, zv.w};
        float xq[4] = {xv.x, xv.y, xv.z, xv.w};
        #pragma unroll
        for (int j = 0; j < 4; j++)
            #pragma unroll
            for (int i = 0; i < 4; i++) {
                ay[j][i] = fmaf(wq[i], xq[j], ay[j][i]);
                az[j][i] = fmaf(zq[i], xq[j], az[j][i]);
            }
    }
    size_t rowbase = ((size_t)b*NN + n0 + ty*4)*CO + tx*4;
    #pragma unroll
    for (int j = 0; j < 4; j++) {
        *(float4*)&g_yT[rowbase + (size_t)j*CO] =
            make_float4(ay[j][0], ay[j][1], ay[j][2], ay[j][3]);
        *(float4*)&g_zT[rowbase + (size_t)j*CO] =
            make_float4(az[j][0], az[j][1], az[j][2], az[j][3]);
    }
}

// ---------------------------------------------------------------------------
// Kernel B: neighbor gather. One warp per (b,n) chunk; lane t owns channels
// t and t+32. Gathers 16 contiguous 256B z-rows (L2 resident), produces
// per-(b,n,o) h extremes and accumulates per-channel sum / sumsq.
// ---------------------------------------------------------------------------
__global__ void __launch_bounds__(256) k_gather(const int* __restrict__ edge) {
    __shared__ float shsum[CO], shq[CO];
    int tid = threadIdx.x;
    int lane = tid & 31;
    int w = tid >> 5;
    if (tid < CO) { shsum[tid] = 0.f; shq[tid] = 0.f; }

    int bn0 = blockIdx.x * 64;        // global row index b*N + n
    int b = bn0 / NN;
    size_t zb = (size_t)b*NN*CO;

    float accs0 = 0.f, accs1 = 0.f, accq0 = 0.f, accq1 = 0.f;

    for (int it = 0; it < 8; it++) {
        int bn = bn0 + w*8 + it;
        size_t base = (size_t)bn*CO;
        float y0 = g_yT[base + lane];
        float y1 = g_yT[base + lane + 32];
        int myidx = edge[bn*KK + (lane & 15)];
        float s10 = 0.f, s11 = 0.f, q0 = 0.f, q1 = 0.f;
        float mn0 = CUDART_INF_F, mn1 = CUDART_INF_F;
        float mx0 = -CUDART_INF_F, mx1 = -CUDART_INF_F;
        #pragma unroll
        for (int k = 0; k < KK; k++) {
            int e = __shfl_sync(0xffffffffu, myidx, k);
            size_t zr = zb + (size_t)e*CO;
            float z0 = g_zT[zr + lane];
            float z1 = g_zT[zr + lane + 32];
            s10 += z0; q0 = fmaf(z0, z0, q0);
            mn0 = fminf(mn0, z0); mx0 = fmaxf(mx0, z0);
            s11 += z1; q1 = fmaf(z1, z1, q1);
            mn1 = fminf(mn1, z1); mx1 = fmaxf(mx1, z1);
        }
        g_hmax[base + lane]      = y0 - mn0;
        g_hmax[base + lane + 32] = y1 - mn1;
        g_hmin[base + lane]      = y0 - mx0;
        g_hmin[base + lane + 32] = y1 - mx1;
        accs0 += (float)KK*y0 - s10;
        accs1 += (float)KK*y1 - s11;
        accq0 += fmaf((float)KK*y0, y0, fmaf(-2.f*y0, s10, q0));
        accq1 += fmaf((float)KK*y1, y1, fmaf(-2.f*y1, s11, q1));
    }
    __syncthreads();
    atomicAdd(&shsum[lane],      accs0);
    atomicAdd(&shsum[lane + 32], accs1);
    atomicAdd(&shq[lane],        accq0);
    atomicAdd(&shq[lane + 32],   accq1);
    __syncthreads();
    if (tid < CO) {
        atomicAdd(&g_sum[tid],   shsum[tid]);
        atomicAdd(&g_sumsq[tid], shq[tid]);
    }
}

// ---------------------------------------------------------------------------
// Kernel C: per-channel BN affine params.  s = gamma*rsqrt(var+eps),
// t = beta - mean*s.
// ---------------------------------------------------------------------------
__global__ void k_stats(const float* __restrict__ gamma,
                        const float* __restrict__ beta) {
    int o = threadIdx.x;
    if (o < CO) {
        const float inv = 1.0f / (float)((long long)BB*NN*KK);
        float mean = g_sum[o] * inv;
        float var  = g_sumsq[o] * inv - mean*mean;
        float s = gamma[o] * rsqrtf(var + 1e-5f);
        g_scale[o] = s;
        g_shift[o] = beta[o] - mean * s;
    }
}

// ---------------------------------------------------------------------------
// Kernel D: epilogue + transpose to output layout (B, CO, N).
// max_k leaky(s*h+t) = leaky(s*hext + t), hext = hmax if s>=0 else hmin
// (leaky o affine is monotone).
// ---------------------------------------------------------------------------
__global__ void __launch_bounds__(256) k_out(float* __restrict__ out) {
    __shared__ float tile[64*65];
    __shared__ float ss[CO], tt[CO];
    int tid = threadIdx.x;
    if (tid < CO) { ss[tid] = g_scale[tid]; tt[tid] = g_shift[tid]; }
    __syncthreads();
    int b = blockIdx.y;
    int n0 = blockIdx.x * 64;
    size_t base = ((size_t)b*NN + n0)*CO;
    for (int i = tid; i < 64*64; i += 256) {
        int nl = i >> 6, o = i & 63;
        float s = ss[o];
        const float* src = (s >= 0.f) ? g_hmax : g_hmin;
        float v = src[base + (size_t)nl*CO + o];
        float h = fmaf(s, v, tt[o]);
        tile[o*65 + nl] = (h >= 0.f) ? h : 0.2f*h;
    }
    __syncthreads();
    size_t ob = (size_t)b*CO*NN + n0;
    for (int i = tid; i < 64*64; i += 256) {
        int o = i >> 6, nl = i & 63;
        out[ob + (size_t)o*NN + nl] = tile[o*65 + nl];
    }
}

extern "C" void kernel_launch(void* const* d_in, const int* in_sizes, int n_in,
                              void* d_out, int out_size) {
    const float* x     = (const float*)d_in[0];
    const int*   edge  = (const int*)d_in[1];
    const float* W     = (const float*)d_in[2];
    const float* gamma = (const float*)d_in[3];
    const float* beta  = (const float*)d_in[4];
    float* out = (float*)d_out;

    dim3 gTile(NN/64, BB);
    k_zero<<<1, 64>>>();
    k_gemm<<<gTile, 256>>>(x, W);
    k_gather<<<BB*NN/64, 256>>>(edge);
    k_stats<<<1, 64>>>(gamma, beta);
    k_out<<<gTile, 256>>>(out);
}

// round 5
// speedup vs baseline: 1.4364x; 1.4364x over previous
#include <cuda_runtime.h>
#include <cuda_bf16.h>
#include <math_constants.h>
#include <cstdint>

#define BB 4
#define CC 64
#define NN 16384
#define KK 16
#define CO 64

// ---------------- scratch globals (no allocation allowed) ----------------
__device__ float g_yT[BB*NN*CO];    // y transposed: [b*N+n][o]
__device__ float g_zT[BB*NN*CO];    // z transposed: [b*N+n][o]
__device__ float g_hmax[BB*NN*CO];  // max_k h = y - min_k z_e
__device__ float g_hmin[BB*NN*CO];  // min_k h = y - max_k z_e
__device__ float g_sum[CO];
__device__ float g_sumsq[CO];
__device__ float g_scale[CO];
__device__ float g_shift[CO];
__device__ int   g_ticket;

// ---------------------------------------------------------------------------
// Kernel A: GEMM via mma.sync m16n8k16 bf16 (PTX sm_80+, works on compute_103).
// Block: 256 threads (8 warps), tile 128 n-rows x 64 out-cols, two B matrices
// (ws = W1+W2 -> yT, w2 = W2 -> zT) processed back to back reusing B smem.
// K=64 fp32 split into bf16 hi/lo; 3 compensation passes per matrix.
// Block 0 also resets the stats accumulators + ticket.
// ---------------------------------------------------------------------------

// XOR-swizzled pair index: row*32 + (pair ^ ((row&7)<<2)); makes the
// m16n8k16 fragment LDS pattern (rows g..g+7 x pairs t4, t4+4) conflict-free.
#define AIDX(r, p) ((r)*32 + ((p) ^ (((r)&7) << 2)))

__global__ void __launch_bounds__(256) k_gemm(const float* __restrict__ x,
                                              const float* __restrict__ W) {
    __shared__ uint32_t Ah[128*32];   // 128 n-rows x 32 k-pairs (bf16x2), 16KB
    __shared__ uint32_t Al[128*32];   // lo part, 16KB
    __shared__ uint32_t Bh[64*32];    // 64 out-rows x 32 k-pairs, 8KB
    __shared__ uint32_t Bl[64*32];    // 8KB   (total 48KB exactly)

    int tid  = threadIdx.x;
    int w    = tid >> 5;
    int lane = tid & 31;
    int g    = lane >> 2;      // group (row within 8)
    int t4   = lane & 3;       // thread-in-group

    if (blockIdx.x == 0) {
        if (tid < CO) { g_sum[tid] = 0.f; g_sumsq[tid] = 0.f; }
        if (tid == 0) g_ticket = 0;
    }

    int bn0  = blockIdx.x * 128;
    int b    = bn0 >> 14;
    int nloc = bn0 & (NN - 1);
    const float* xb = x + ((size_t)b << 20) + nloc;   // b*C*N

    // ---- fill A (transpose x[c][n] -> A[n][c], bf16 hi/lo, swizzled) ----
    for (int i = tid; i < 128*32; i += 256) {
        int n = i & 127, p = i >> 7;               // consecutive tid -> n: gmem coalesced
        float v0 = xb[(size_t)(2*p)   * NN + n];
        float v1 = xb[(size_t)(2*p+1) * NN + n];
        __nv_bfloat162 h2 = __floats2bfloat162_rn(v0, v1);
        uint32_t hp = ((uint32_t)__bfloat16_as_ushort(h2.y) << 16) | __bfloat16_as_ushort(h2.x);
        float l0 = v0 - __bfloat162float(h2.x);
        float l1 = v1 - __bfloat162float(h2.y);
        __nv_bfloat162 l2 = __floats2bfloat162_rn(l0, l1);
        uint32_t lp = ((uint32_t)__bfloat16_as_ushort(l2.y) << 16) | __bfloat16_as_ushort(l2.x);
        int idx = AIDX(n, p);
        Ah[idx] = hp;
        Al[idx] = lp;
    }

    int m0 = w * 16;   // this warp's 16-row group

    float acc[8][4];

    #pragma unroll 1
    for (int mat = 0; mat < 2; mat++) {
        // ---- fill B for this matrix ----
        __syncthreads();   // (mat 1: wait until all warps done reading old B)
        for (int i = tid; i < 64*32; i += 256) {
            int p = i & 31, j = i >> 5;
            float v0, v1;
            if (mat == 0) {
                v0 = W[j*128 + 2*p]     + W[j*128 + 64 + 2*p];
                v1 = W[j*128 + 2*p + 1] + W[j*128 + 64 + 2*p + 1];
            } else {
                v0 = W[j*128 + 64 + 2*p];
                v1 = W[j*128 + 64 + 2*p + 1];
            }
            __nv_bfloat162 h2 = __floats2bfloat162_rn(v0, v1);
            uint32_t hp = ((uint32_t)__bfloat16_as_ushort(h2.y) << 16) | __bfloat16_as_ushort(h2.x);
            float l0 = v0 - __bfloat162float(h2.x);
            float l1 = v1 - __bfloat162float(h2.y);
            __nv_bfloat162 l2 = __floats2bfloat162_rn(l0, l1);
            uint32_t lp = ((uint32_t)__bfloat16_as_ushort(l2.y) << 16) | __bfloat16_as_ushort(l2.x);
            int idx = AIDX(j, p);
            Bh[idx] = hp;
            Bl[idx] = lp;
        }
        __syncthreads();

        #pragma unroll
        for (int ct = 0; ct < 8; ct++)
            #pragma unroll
            for (int q = 0; q < 4; q++) acc[ct][q] = 0.f;

        // ---- 3 compensation passes x 4 k-steps ----
        #pragma unroll 1
        for (int pass = 0; pass < 3; pass++) {
            const uint32_t* Asrc = (pass == 1) ? Al : Ah;
            const uint32_t* Bsrc = (pass == 2) ? Bl : Bh;
            #pragma unroll
            for (int ks = 0; ks < 4; ks++) {
                uint32_t a0 = Asrc[AIDX(m0 + g,     ks*8 + t4)];
                uint32_t a1 = Asrc[AIDX(m0 + g + 8, ks*8 + t4)];
                uint32_t a2 = Asrc[AIDX(m0 + g,     ks*8 + t4 + 4)];
                uint32_t a3 = Asrc[AIDX(m0 + g + 8, ks*8 + t4 + 4)];
                #pragma unroll
                for (int ct = 0; ct < 8; ct++) {
                    int o = ct*8 + g;
                    uint32_t b0 = Bsrc[AIDX(o, ks*8 + t4)];
                    uint32_t b1 = Bsrc[AIDX(o, ks*8 + t4 + 4)];
                    asm volatile(
                        "mma.sync.aligned.m16n8k16.row.col.f32.bf16.bf16.f32 "
                        "{%0,%1,%2,%3},{%4,%5,%6,%7},{%8,%9},{%0,%1,%2,%3};"
                        : "+f"(acc[ct][0]), "+f"(acc[ct][1]),
                          "+f"(acc[ct][2]), "+f"(acc[ct][3])
                        : "r"(a0), "r"(a1), "r"(a2), "r"(a3), "r"(b0), "r"(b1));
                }
            }
        }

        // ---- store: lane (g,t4) owns cols ct*8 + 2*t4 (+1), rows m0+g, +8 ----
        float* dst = (mat == 0) ? g_yT : g_zT;
        size_t r0 = (size_t)(bn0 + m0 + g) * CO;
        size_t r1 = r0 + 8*CO;
        #pragma unroll
        for (int ct = 0; ct < 8; ct++) {
            int o = ct*8 + 2*t4;
            *(float2*)&dst[r0 + o] = make_float2(acc[ct][0], acc[ct][1]);
            *(float2*)&dst[r1 + o] = make_float2(acc[ct][2], acc[ct][3]);
        }
    }
}

// ---------------------------------------------------------------------------
// Kernel B: neighbor gather + stats (last block computes BN affine params).
// ---------------------------------------------------------------------------
__global__ void __launch_bounds__(256) k_gather(const int* __restrict__ edge,
                                                const float* __restrict__ gamma,
                                                const float* __restrict__ beta) {
    __shared__ float shsum[CO], shq[CO];
    __shared__ int s_last;
    int tid = threadIdx.x;
    int lane = tid & 31;
    int w = tid >> 5;
    if (tid < CO) { shsum[tid] = 0.f; shq[tid] = 0.f; }

    int bn0 = blockIdx.x * 64;
    int b = bn0 / NN;
    size_t zb = (size_t)b*NN*CO;

    float accs0 = 0.f, accs1 = 0.f, accq0 = 0.f, accq1 = 0.f;

    for (int it = 0; it < 8; it++) {
        int bn = bn0 + w*8 + it;
        size_t base = (size_t)bn*CO;
        float y0 = g_yT[base + lane];
        float y1 = g_yT[base + lane + 32];
        int myidx = edge[bn*KK + (lane & 15)];
        float s10 = 0.f, s11 = 0.f, q0 = 0.f, q1 = 0.f;
        float mn0 = CUDART_INF_F, mn1 = CUDART_INF_F;
        float mx0 = -CUDART_INF_F, mx1 = -CUDART_INF_F;
        #pragma unroll
        for (int k = 0; k < KK; k++) {
            int e = __shfl_sync(0xffffffffu, myidx, k);
            size_t zr = zb + (size_t)e*CO;
            float z0 = g_zT[zr + lane];
            float z1 = g_zT[zr + lane + 32];
            s10 += z0; q0 = fmaf(z0, z0, q0);
            mn0 = fminf(mn0, z0); mx0 = fmaxf(mx0, z0);
            s11 += z1; q1 = fmaf(z1, z1, q1);
            mn1 = fminf(mn1, z1); mx1 = fmaxf(mx1, z1);
        }
        g_hmax[base + lane]      = y0 - mn0;
        g_hmax[base + lane + 32] = y1 - mn1;
        g_hmin[base + lane]      = y0 - mx0;
        g_hmin[base + lane + 32] = y1 - mx1;
        accs0 += (float)KK*y0 - s10;
        accs1 += (float)KK*y1 - s11;
        accq0 += fmaf((float)KK*y0, y0, fmaf(-2.f*y0, s10, q0));
        accq1 += fmaf((float)KK*y1, y1, fmaf(-2.f*y1, s11, q1));
    }
    __syncthreads();
    atomicAdd(&shsum[lane],      accs0);
    atomicAdd(&shsum[lane + 32], accs1);
    atomicAdd(&shq[lane],        accq0);
    atomicAdd(&shq[lane + 32],   accq1);
    __syncthreads();
    if (tid < CO) {
        atomicAdd(&g_sum[tid],   shsum[tid]);
        atomicAdd(&g_sumsq[tid], shq[tid]);
    }
    __threadfence();
    __syncthreads();
    if (tid == 0) s_last = (atomicAdd(&g_ticket, 1) == (int)gridDim.x - 1);
    __syncthreads();
    if (s_last && tid < CO) {
        const float inv = 1.0f / (float)((long long)BB*NN*KK);
        float sm = atomicAdd(&g_sum[tid],   0.f);
        float sq = atomicAdd(&g_sumsq[tid], 0.f);
        float mean = sm * inv;
        float var  = sq * inv - mean*mean;
        float s = gamma[tid] * rsqrtf(var + 1e-5f);
        g_scale[tid] = s;
        g_shift[tid] = beta[tid] - mean * s;
    }
}

// ---------------------------------------------------------------------------
// Kernel C: epilogue + transpose to output layout (B, CO, N).
// max_k leaky(s*h+t) = leaky(s*hext + t), hext = hmax if s>=0 else hmin.
// ---------------------------------------------------------------------------
__global__ void __launch_bounds__(256) k_out(float* __restrict__ out) {
    __shared__ float tile[64*65];
    __shared__ float ss[CO], tt[CO];
    int tid = threadIdx.x;
    if (tid < CO) { ss[tid] = g_scale[tid]; tt[tid] = g_shift[tid]; }
    __syncthreads();
    int b = blockIdx.y;
    int n0 = blockIdx.x * 64;
    size_t base = ((size_t)b*NN + n0)*CO;
    for (int i = tid; i < 64*64; i += 256) {
        int nl = i >> 6, o = i & 63;
        float s = ss[o];
        const float* src = (s >= 0.f) ? g_hmax : g_hmin;
        float v = src[base + (size_t)nl*CO + o];
        float h = fmaf(s, v, tt[o]);
        tile[o*65 + nl] = (h >= 0.f) ? h : 0.2f*h;
    }
    __syncthreads();
    size_t ob = (size_t)b*CO*NN + n0;
    for (int i = tid; i < 64*64; i += 256) {
        int o = i >> 6, nl = i & 63;
        out[ob + (size_t)o*NN + nl] = tile[o*65 + nl];
    }
}

extern "C" void kernel_launch(void* const* d_in, const int* in_sizes, int n_in,
                              void* d_out, int out_size) {
    const float* x     = (const float*)d_in[0];
    const int*   edge  = (const int*)d_in[1];
    const float* W     = (const float*)d_in[2];
    const float* gamma = (const float*)d_in[3];
    const float* beta  = (const float*)d_in[4];
    float* out = (float*)d_out;

    k_gemm<<<BB*NN/128, 256>>>(x, W);
    k_gather<<<BB*NN/64, 256>>>(edge, gamma, beta);
    k_out<<<dim3(NN/64, BB), 256>>>(out);
}